// round 4
// baseline (speedup 1.0000x reference)
#include <cuda_runtime.h>
#include <cstdint>

// MoEAllReduce: fused expert-weighted reduction + residual add + RMSNorm.
// out[0 : T*H]     = hidden_states
// out[T*H : 2*T*H] = output_residual
//
// Persistent kernel: grid = 148*5 CTAs (one full resident wave), each CTA
// loops over token rows with stride gridDim.x. 256 threads, 4 float4
// chunks/thread (H=4096). Batched load phase -> block reduce -> batched
// store phase. Streaming cache hints on all zero-reuse streams.

#define NTHREADS 256
#define MAX_ITEMS 16   // fallback path supports H up to 4*256*16 = 16384

__device__ __forceinline__ float warp_reduce_sum(float v) {
#pragma unroll
    for (int off = 16; off > 0; off >>= 1)
        v += __shfl_xor_sync(0xFFFFFFFFu, v, off);
    return v;
}

template <int E_T, int ITEMS_T>
__global__ __launch_bounds__(NTHREADS, 5)
void moe_allreduce_rmsnorm_kernel(
    const float* __restrict__ residual,     // [T, H]
    const float* __restrict__ norm_weight,  // [H]
    const float* __restrict__ scale,        // [E, T]
    const float* __restrict__ A,            // [E, T, H]
    const float* __restrict__ token,        // [T, H]
    float* __restrict__ hidden,             // [T, H]
    float* __restrict__ out_res,            // [T, H]
    int E, int T, int H)
{
    const int tid = threadIdx.x;
    const int h4 = H >> 2;                   // float4 count per row
    const int items = (ITEMS_T > 0) ? ITEMS_T : (h4 / NTHREADS);
    const size_t rowStride4 = (size_t)T * h4;   // float4 stride between experts

    __shared__ float s_scale[32];
    __shared__ float s_warp[NTHREADS / 32];
    __shared__ float s_inv;

    const int Eeff = (E_T > 0) ? E_T : E;
    const int wid = tid >> 5;
    const int lid = tid & 31;

    for (int t = blockIdx.x; t < T; t += gridDim.x) {

        // Per-row scales. Barrier below also separates this row's s_inv
        // from the previous row's reads (s_inv read happened before the
        // previous store loop's end... ensure no hazard: previous iteration's
        // last read of s_inv is before its stores; this write is guarded by
        // __syncthreads here).
        __syncthreads();
        if (tid < Eeff) s_scale[tid] = scale[(size_t)tid * T + t];
        __syncthreads();

        const float4* __restrict__ res4 = (const float4*)(residual + (size_t)t * H);
        const float4* __restrict__ tok4 = (const float4*)(token    + (size_t)t * H);
        const float4* __restrict__ A4   = (const float4*)A;
        const size_t rowBase4 = (size_t)t * h4;

        float4 acc[ITEMS_T > 0 ? ITEMS_T : MAX_ITEMS];
        float ss = 0.0f;

#pragma unroll
        for (int i = 0; i < (ITEMS_T > 0 ? ITEMS_T : MAX_ITEMS); i++) {
            if (ITEMS_T == 0 && i >= items) break;
            const int idx = tid + i * NTHREADS;   // fully coalesced
            float4 r = __ldcs(&res4[idx]);
            float4 k = __ldcs(&tok4[idx]);
            float4 a;
            a.x = r.x + k.x; a.y = r.y + k.y; a.z = r.z + k.z; a.w = r.w + k.w;

            if (E_T > 0) {
#pragma unroll
                for (int e = 0; e < E_T; e++) {
                    const float se = s_scale[e];
                    float4 v = __ldcs(&A4[(size_t)e * rowStride4 + rowBase4 + idx]);
                    a.x = fmaf(se, v.x, a.x);
                    a.y = fmaf(se, v.y, a.y);
                    a.z = fmaf(se, v.z, a.z);
                    a.w = fmaf(se, v.w, a.w);
                }
            } else {
                for (int e = 0; e < E; e++) {
                    const float se = s_scale[e];
                    float4 v = __ldcs(&A4[(size_t)e * rowStride4 + rowBase4 + idx]);
                    a.x = fmaf(se, v.x, a.x);
                    a.y = fmaf(se, v.y, a.y);
                    a.z = fmaf(se, v.z, a.z);
                    a.w = fmaf(se, v.w, a.w);
                }
            }

            acc[i] = a;
            ss += a.x * a.x + a.y * a.y + a.z * a.z + a.w * a.w;
        }

        // Block reduction of sum-of-squares
        ss = warp_reduce_sum(ss);
        if (lid == 0) s_warp[wid] = ss;
        __syncthreads();
        if (wid == 0) {
            float v = (lid < NTHREADS / 32) ? s_warp[lid] : 0.0f;
            v = warp_reduce_sum(v);
            if (lid == 0) s_inv = rsqrtf(v / (float)H + 1e-5f);
        }
        __syncthreads();
        const float inv = s_inv;

        const float4* __restrict__ w4 = (const float4*)norm_weight;
        float4* __restrict__ o_res4 = (float4*)(out_res + (size_t)t * H);
        float4* __restrict__ o_hid4 = (float4*)(hidden  + (size_t)t * H);

        // Batched store phase: both outputs, writes grouped together.
#pragma unroll
        for (int i = 0; i < (ITEMS_T > 0 ? ITEMS_T : MAX_ITEMS); i++) {
            if (ITEMS_T == 0 && i >= items) break;
            const int idx = tid + i * NTHREADS;
            float4 a = acc[i];
            float4 w = __ldg(&w4[idx]);           // L2-resident broadcast
            float4 hOut;
            hOut.x = a.x * inv * w.x;
            hOut.y = a.y * inv * w.y;
            hOut.z = a.z * inv * w.z;
            hOut.w = a.w * inv * w.w;
            __stcs(&o_res4[idx], a);
            __stcs(&o_hid4[idx], hOut);
        }
    }
}

extern "C" void kernel_launch(void* const* d_in, const int* in_sizes, int n_in,
                              void* d_out, int out_size)
{
    const float* residual = (const float*)d_in[0];   // [T, H]
    const float* weight   = (const float*)d_in[1];   // [H]
    const float* scale    = (const float*)d_in[2];   // [E, T]
    const float* A        = (const float*)d_in[3];   // [E, T, H]
    const float* token    = (const float*)d_in[4];   // [T, H]

    const int H = in_sizes[1];
    const int TH = in_sizes[0];
    const int T = TH / H;
    const int E = in_sizes[2] / T;

    float* hidden  = (float*)d_out;              // [T, H]
    float* out_res = (float*)d_out + (size_t)TH; // [T, H]

    // One fully-resident persistent wave: 152 SMs on GB300, 5 CTAs/SM.
    // (148 on B300 — use device query-free conservative 148; extra CTAs
    // beyond residency would just form a tiny second wave, so prefer the
    // exact resident count via occupancy: 5 * numSMs.)
    int numSMs = 148;
    cudaDeviceGetAttribute(&numSMs, cudaDevAttrMultiProcessorCount, 0);
    int grid = numSMs * 5;
    if (grid > T) grid = T;

    dim3 block(NTHREADS);
    const int h4 = H >> 2;
    if (E == 8 && h4 == 4 * NTHREADS) {
        moe_allreduce_rmsnorm_kernel<8, 4><<<grid, block>>>(
            residual, weight, scale, A, token, hidden, out_res, E, T, H);
    } else {
        moe_allreduce_rmsnorm_kernel<0, 0><<<grid, block>>>(
            residual, weight, scale, A, token, hidden, out_res, E, T, H);
    }
}

// round 5
// speedup vs baseline: 1.0273x; 1.0273x over previous
#include <cuda_runtime.h>
#include <cstdint>

// MoEAllReduce: fused expert-weighted reduction + residual add + RMSNorm.
// out[0 : T*H]     = hidden_states
// out[T*H : 2*T*H] = output_residual
//
// One CTA per token row t (non-persistent; HW work-stealing handles waves).
// 512 threads, 2 float4 chunks/thread (H=4096), __launch_bounds__(512,3)
// -> 1536 threads/SM. Batched load phase -> block reduce -> batched store
// phase. Streaming cache hints (__ldcs/__stcs) on all zero-reuse streams.

#define NTHREADS 512
#define MAX_ITEMS 8   // fallback path supports H up to 4*512*8 = 16384

__device__ __forceinline__ float warp_reduce_sum(float v) {
#pragma unroll
    for (int off = 16; off > 0; off >>= 1)
        v += __shfl_xor_sync(0xFFFFFFFFu, v, off);
    return v;
}

template <int E_T, int ITEMS_T>
__global__ __launch_bounds__(NTHREADS, 3)
void moe_allreduce_rmsnorm_kernel(
    const float* __restrict__ residual,     // [T, H]
    const float* __restrict__ norm_weight,  // [H]
    const float* __restrict__ scale,        // [E, T]
    const float* __restrict__ A,            // [E, T, H]
    const float* __restrict__ token,        // [T, H]
    float* __restrict__ hidden,             // [T, H]
    float* __restrict__ out_res,            // [T, H]
    int E, int T, int H)
{
    const int t = blockIdx.x;
    const int tid = threadIdx.x;
    const int h4 = H >> 2;                   // float4 count per row
    const int items = (ITEMS_T > 0) ? ITEMS_T : (h4 / NTHREADS);

    __shared__ float s_scale[32];
    __shared__ float s_warp[NTHREADS / 32];
    __shared__ float s_inv;

    const int Eeff = (E_T > 0) ? E_T : E;
    if (tid < Eeff) s_scale[tid] = scale[(size_t)tid * T + t];
    __syncthreads();

    const float4* __restrict__ res4 = (const float4*)(residual + (size_t)t * H);
    const float4* __restrict__ tok4 = (const float4*)(token    + (size_t)t * H);
    const float4* __restrict__ A4   = (const float4*)A;
    const size_t rowStride4 = (size_t)T * h4;   // float4 stride between experts
    const size_t rowBase4   = (size_t)t * h4;

    float4 acc[ITEMS_T > 0 ? ITEMS_T : MAX_ITEMS];
    float ss = 0.0f;

#pragma unroll
    for (int i = 0; i < (ITEMS_T > 0 ? ITEMS_T : MAX_ITEMS); i++) {
        if (ITEMS_T == 0 && i >= items) break;
        const int idx = tid + i * NTHREADS;   // fully coalesced
        float4 r = __ldcs(&res4[idx]);
        float4 k = __ldcs(&tok4[idx]);
        float4 a;
        a.x = r.x + k.x; a.y = r.y + k.y; a.z = r.z + k.z; a.w = r.w + k.w;

        if (E_T > 0) {
#pragma unroll
            for (int e = 0; e < E_T; e++) {
                const float se = s_scale[e];
                float4 v = __ldcs(&A4[(size_t)e * rowStride4 + rowBase4 + idx]);
                a.x = fmaf(se, v.x, a.x);
                a.y = fmaf(se, v.y, a.y);
                a.z = fmaf(se, v.z, a.z);
                a.w = fmaf(se, v.w, a.w);
            }
        } else {
            for (int e = 0; e < E; e++) {
                const float se = s_scale[e];
                float4 v = __ldcs(&A4[(size_t)e * rowStride4 + rowBase4 + idx]);
                a.x = fmaf(se, v.x, a.x);
                a.y = fmaf(se, v.y, a.y);
                a.z = fmaf(se, v.z, a.z);
                a.w = fmaf(se, v.w, a.w);
            }
        }

        acc[i] = a;
        ss += a.x * a.x + a.y * a.y + a.z * a.z + a.w * a.w;
    }

    // Block reduction of sum-of-squares
    ss = warp_reduce_sum(ss);
    const int wid = tid >> 5;
    const int lid = tid & 31;
    if (lid == 0) s_warp[wid] = ss;
    __syncthreads();
    if (wid == 0) {
        float v = (lid < NTHREADS / 32) ? s_warp[lid] : 0.0f;
        v = warp_reduce_sum(v);
        if (lid == 0) s_inv = rsqrtf(v / (float)H + 1e-5f);
    }
    __syncthreads();
    const float inv = s_inv;

    const float4* __restrict__ w4 = (const float4*)norm_weight;
    float4* __restrict__ o_res4 = (float4*)(out_res + (size_t)t * H);
    float4* __restrict__ o_hid4 = (float4*)(hidden  + (size_t)t * H);

    // Batched store phase: both outputs, writes grouped together.
#pragma unroll
    for (int i = 0; i < (ITEMS_T > 0 ? ITEMS_T : MAX_ITEMS); i++) {
        if (ITEMS_T == 0 && i >= items) break;
        const int idx = tid + i * NTHREADS;
        float4 a = acc[i];
        float4 w = __ldg(&w4[idx]);           // L2-resident broadcast
        float4 hOut;
        hOut.x = a.x * inv * w.x;
        hOut.y = a.y * inv * w.y;
        hOut.z = a.z * inv * w.z;
        hOut.w = a.w * inv * w.w;
        __stcs(&o_res4[idx], a);
        __stcs(&o_hid4[idx], hOut);
    }
}

extern "C" void kernel_launch(void* const* d_in, const int* in_sizes, int n_in,
                              void* d_out, int out_size)
{
    const float* residual = (const float*)d_in[0];   // [T, H]
    const float* weight   = (const float*)d_in[1];   // [H]
    const float* scale    = (const float*)d_in[2];   // [E, T]
    const float* A        = (const float*)d_in[3];   // [E, T, H]
    const float* token    = (const float*)d_in[4];   // [T, H]

    const int H = in_sizes[1];
    const int TH = in_sizes[0];
    const int T = TH / H;
    const int E = in_sizes[2] / T;

    float* hidden  = (float*)d_out;              // [T, H]
    float* out_res = (float*)d_out + (size_t)TH; // [T, H]

    dim3 grid(T);
    dim3 block(NTHREADS);
    const int h4 = H >> 2;
    if (E == 8 && h4 == 2 * NTHREADS) {
        moe_allreduce_rmsnorm_kernel<8, 2><<<grid, block>>>(
            residual, weight, scale, A, token, hidden, out_res, E, T, H);
    } else {
        moe_allreduce_rmsnorm_kernel<0, 0><<<grid, block>>>(
            residual, weight, scale, A, token, hidden, out_res, E, T, H);
    }
}